// round 2
// baseline (speedup 1.0000x reference)
#include <cuda_runtime.h>
#include <math.h>

#define N_  256
#define M_  256
#define D_  256
#define E_  128
#define H_  4
#define HD_ 32
#define P_  64
#define CH_ 128   // key chunks (split-K over the 256 key tiles)
#define TPC 2     // tiles (of 256 keys) per chunk

// ---------------- device scratch (static, no allocations) ----------------
__device__ float d_q[N_*E_];                       // scaled queries [N][E]
__device__ float d_phix[N_*E_], d_phiy[M_*E_];
__device__ float d_gx[N_*E_],  d_gy[M_*E_];
__device__ float d_Wkp[E_*P_], d_Wkg[E_*P_];       // folded MLP2 @ proj weights
__device__ float d_bkp[E_],    d_bkg[E_];
__device__ float d_pm[H_*CH_*N_], d_pl[H_*CH_*N_]; // partial softmax stats
__device__ float d_po[H_*CH_*N_*HD_];              // partial outputs
__device__ float d_of[N_*E_];                      // combined attention out

// ---------------- A1: fold phi_w[:,D:] @ k_w2 -> Wkp (and g_w -> Wkg) ----
__global__ void kfold(const float* __restrict__ phi_w, const float* __restrict__ g_w,
                      const float* __restrict__ k_w2, const float* __restrict__ k_b2) {
    int e = blockIdx.x, t = threadIdx.x;   // 128 threads
    if (t < 64) {
        int p = t; float a = 0.f;
        for (int ep = 0; ep < 128; ep++)
            a = fmaf(phi_w[e*384 + 256 + ep], k_w2[ep*64 + p], a);
        d_Wkp[e*64 + p] = a;
    } else {
        int p = t - 64; float a = 0.f;
        for (int ep = 0; ep < 128; ep++)
            a = fmaf(g_w[e*384 + 256 + ep], k_w2[ep*64 + p], a);
        d_Wkg[e*64 + p] = a;
    }
    if (t == 0) {
        float a = 0.f;
        for (int ep = 0; ep < 128; ep++) a = fmaf(phi_w[e*384 + 256 + ep], k_b2[ep], a);
        d_bkp[e] = a;
    }
    if (t == 64) {
        float a = 0.f;
        for (int ep = 0; ep < 128; ep++) a = fmaf(g_w[e*384 + 256 + ep], k_b2[ep], a);
        d_bkg[e] = a;
    }
}

// ---------------- A2: queries (pos-MLP + concat-proj + scaling) ----------
__global__ void kq(const float* __restrict__ x, const float* __restrict__ x_pos,
                   const float* __restrict__ theta_w,
                   const float* __restrict__ q_w1, const float* __restrict__ q_b1,
                   const float* __restrict__ q_w2, const float* __restrict__ q_b2) {
    int n = blockIdx.x, t = threadIdx.x;   // 128 threads
    __shared__ float hq[64], qpe[128], sx[256];
    float xp0 = x_pos[n*3], xp1 = x_pos[n*3+1], xp2 = x_pos[n*3+2];
    if (t < 64)
        hq[t] = fmaxf(0.f, fmaf(q_w1[t*3], xp0, fmaf(q_w1[t*3+1], xp1,
                     fmaf(q_w1[t*3+2], xp2, q_b1[t]))));
    sx[t]       = x[n*256 + t];
    sx[t + 128] = x[n*256 + t + 128];
    __syncthreads();
    float a = q_b2[t];
    for (int p = 0; p < 64; p++) a = fmaf(hq[p], q_w2[t*64 + p], a);
    qpe[t] = a;
    __syncthreads();
    float s = 0.f;
    const float* tw = theta_w + t*384;
    #pragma unroll 8
    for (int d = 0; d < 256; d++) s = fmaf(sx[d], tw[d], s);
    #pragma unroll 8
    for (int e = 0; e < 128; e++) s = fmaf(qpe[e], tw[256 + e], s);
    d_q[n*128 + t] = s * 0.17677669529663687f;   // HD^-0.5
}

// ---------------- A3: small projections x/y @ W[:, :D]^T -----------------
__global__ void kproj(const float* __restrict__ x, const float* __restrict__ y,
                      const float* __restrict__ phi_w, const float* __restrict__ g_w) {
    int n = blockIdx.x, which = blockIdx.y, t = threadIdx.x;  // 128 threads
    const float* src = (which & 1) ? y : x;
    const float* w   = (which < 2) ? phi_w : g_w;
    float* out = (which == 0) ? d_phix : (which == 1) ? d_phiy
               : (which == 2) ? d_gx   : d_gy;
    __shared__ float sx[256];
    sx[t]       = src[n*256 + t];
    sx[t + 128] = src[n*256 + t + 128];
    __syncthreads();
    float a = 0.f;
    const float* wr = w + t*384;
    #pragma unroll 8
    for (int d = 0; d < 256; d++) a = fmaf(sx[d], wr[d], a);
    out[n*128 + t] = a;
}

// ---------------- B: fused kv-gen + flash attention (split-K) ------------
// grid (CH_, H_), 256 threads. Thread t = query index AND per-tile key row n.
__global__ void __launch_bounds__(256, 2)
kattn(const float* __restrict__ x_pos, const float* __restrict__ y_pos,
      const float* __restrict__ k_w1, const float* __restrict__ k_b1) {
    extern __shared__ float sm[];
    float* ks   = sm;            // [256][36]
    float* vs   = sm + 9216;     // [256][36]
    float* WkpT = sm + 18432;    // [64][32]  (transposed head slice)
    float* WkgT = sm + 20480;    // [64][32]
    float* kw1s = sm + 22528;    // [64*3]
    float* kb1s = sm + 22720;    // [64]
    float* bkps = sm + 22784;    // [32]
    float* bkgs = sm + 22816;    // [32]   total 22848 floats

    int h = blockIdx.y, c = blockIdx.x, t = threadIdx.x;

    for (int i = t; i < 2048; i += 256) {
        int p = i >> 5, d = i & 31;
        WkpT[i] = d_Wkp[(h*32 + d)*64 + p];
        WkgT[i] = d_Wkg[(h*32 + d)*64 + p];
    }
    for (int i = t; i < 192; i += 256) kw1s[i] = k_w1[i];
    if (t < 64) kb1s[t] = k_b1[t];
    if (t < 32) { bkps[t] = d_bkp[h*32 + t]; bkgs[t] = d_bkg[h*32 + t]; }
    __syncthreads();

    float4 q4[8];
    {
        const float4* qp = (const float4*)(d_q + t*E_ + h*HD_);
        #pragma unroll
        for (int i = 0; i < 8; i++) q4[i] = qp[i];
    }
    float o[32];
    #pragma unroll
    for (int i = 0; i < 32; i++) o[i] = 0.f;
    float mr = -INFINITY, lr = 0.f;

    float xp0 = x_pos[t*3], xp1 = x_pos[t*3+1], xp2 = x_pos[t*3+2];

    for (int it = 0; it < TPC; ++it) {
        int m = c*TPC + it;      // tile index == m; key j = m*256 + n, n = t
        float r0 = xp0 - y_pos[m*3];
        float r1 = xp1 - y_pos[m*3+1];
        float r2 = xp2 - y_pos[m*3+2];

        float acc[32];
        // ---- k row for key (m, n=t), head slice ----
        {
            const float4* px = (const float4*)(d_phix + t*E_ + h*HD_);
            const float4* py = (const float4*)(d_phiy + m*E_ + h*HD_);
            #pragma unroll
            for (int dq = 0; dq < 8; dq++) {
                float4 a = px[dq], b = py[dq];
                acc[4*dq+0] = a.x - b.x + bkps[4*dq+0];
                acc[4*dq+1] = a.y - b.y + bkps[4*dq+1];
                acc[4*dq+2] = a.z - b.z + bkps[4*dq+2];
                acc[4*dq+3] = a.w - b.w + bkps[4*dq+3];
            }
        }
        #pragma unroll 4
        for (int p = 0; p < 64; p++) {
            float h1 = fmaxf(0.f, fmaf(kw1s[p*3], r0, fmaf(kw1s[p*3+1], r1,
                            fmaf(kw1s[p*3+2], r2, kb1s[p]))));
            const float4* w4 = (const float4*)(WkpT + p*32);
            #pragma unroll
            for (int dq = 0; dq < 8; dq++) {
                float4 w = w4[dq];
                acc[4*dq+0] = fmaf(h1, w.x, acc[4*dq+0]);
                acc[4*dq+1] = fmaf(h1, w.y, acc[4*dq+1]);
                acc[4*dq+2] = fmaf(h1, w.z, acc[4*dq+2]);
                acc[4*dq+3] = fmaf(h1, w.w, acc[4*dq+3]);
            }
        }
        {
            float4* kd = (float4*)(ks + t*36);
            #pragma unroll
            for (int dq = 0; dq < 8; dq++)
                kd[dq] = make_float4(acc[4*dq], acc[4*dq+1], acc[4*dq+2], acc[4*dq+3]);
        }
        // ---- v row (reuse acc) ----
        {
            const float4* px = (const float4*)(d_gx + t*E_ + h*HD_);
            const float4* py = (const float4*)(d_gy + m*E_ + h*HD_);
            #pragma unroll
            for (int dq = 0; dq < 8; dq++) {
                float4 a = px[dq], b = py[dq];
                acc[4*dq+0] = a.x - b.x + bkgs[4*dq+0];
                acc[4*dq+1] = a.y - b.y + bkgs[4*dq+1];
                acc[4*dq+2] = a.z - b.z + bkgs[4*dq+2];
                acc[4*dq+3] = a.w - b.w + bkgs[4*dq+3];
            }
        }
        #pragma unroll 4
        for (int p = 0; p < 64; p++) {
            float h1 = fmaxf(0.f, fmaf(kw1s[p*3], r0, fmaf(kw1s[p*3+1], r1,
                            fmaf(kw1s[p*3+2], r2, kb1s[p]))));
            const float4* w4 = (const float4*)(WkgT + p*32);
            #pragma unroll
            for (int dq = 0; dq < 8; dq++) {
                float4 w = w4[dq];
                acc[4*dq+0] = fmaf(h1, w.x, acc[4*dq+0]);
                acc[4*dq+1] = fmaf(h1, w.y, acc[4*dq+1]);
                acc[4*dq+2] = fmaf(h1, w.z, acc[4*dq+2]);
                acc[4*dq+3] = fmaf(h1, w.w, acc[4*dq+3]);
            }
        }
        {
            float4* vd = (float4*)(vs + t*36);
            #pragma unroll
            for (int dq = 0; dq < 8; dq++)
                vd[dq] = make_float4(acc[4*dq], acc[4*dq+1], acc[4*dq+2], acc[4*dq+3]);
        }
        __syncthreads();

        // ---- online-softmax attention over this 256-key tile ----
        for (int kb = 0; kb < 256; kb += 8) {
            float s[8];
            #pragma unroll
            for (int k8 = 0; k8 < 8; k8++) {
                const float4* kk = (const float4*)(ks + (kb + k8)*36);
                float a0 = 0.f, a1 = 0.f, a2 = 0.f, a3 = 0.f;
                #pragma unroll
                for (int dq = 0; dq < 8; dq++) {
                    float4 kv = kk[dq];
                    a0 = fmaf(q4[dq].x, kv.x, a0);
                    a1 = fmaf(q4[dq].y, kv.y, a1);
                    a2 = fmaf(q4[dq].z, kv.z, a2);
                    a3 = fmaf(q4[dq].w, kv.w, a3);
                }
                s[k8] = (a0 + a1) + (a2 + a3);
            }
            float mn = mr;
            #pragma unroll
            for (int k8 = 0; k8 < 8; k8++) mn = fmaxf(mn, s[k8]);
            float scale = __expf(mr - mn);
            float ls = 0.f;
            #pragma unroll
            for (int k8 = 0; k8 < 8; k8++) { s[k8] = __expf(s[k8] - mn); ls += s[k8]; }
            lr = fmaf(lr, scale, ls);
            mr = mn;
            #pragma unroll
            for (int i = 0; i < 32; i++) o[i] *= scale;
            #pragma unroll
            for (int k8 = 0; k8 < 8; k8++) {
                const float4* vv = (const float4*)(vs + (kb + k8)*36);
                float pk = s[k8];
                #pragma unroll
                for (int dq = 0; dq < 8; dq++) {
                    float4 v = vv[dq];
                    o[4*dq+0] = fmaf(pk, v.x, o[4*dq+0]);
                    o[4*dq+1] = fmaf(pk, v.y, o[4*dq+1]);
                    o[4*dq+2] = fmaf(pk, v.z, o[4*dq+2]);
                    o[4*dq+3] = fmaf(pk, v.w, o[4*dq+3]);
                }
            }
        }
        __syncthreads();
    }

    int base = (h*CH_ + c)*N_ + t;
    d_pm[base] = mr;
    d_pl[base] = lr;
    float4* op = (float4*)(d_po + (size_t)base*32);
    #pragma unroll
    for (int dq = 0; dq < 8; dq++)
        op[dq] = make_float4(o[4*dq], o[4*dq+1], o[4*dq+2], o[4*dq+3]);
}

// ---------------- C: split-K softmax combine -----------------------------
__global__ void kcomb() {
    int bid = blockIdx.x;            // 1024 = H*N
    int h = bid >> 8, nq = bid & 255;
    int d = threadIdx.x;             // 32
    float Mx = -INFINITY;
    for (int c = 0; c < CH_; c++)
        Mx = fmaxf(Mx, d_pm[(h*CH_ + c)*N_ + nq]);
    float L = 0.f, oa = 0.f;
    for (int c = 0; c < CH_; c++) {
        int b = (h*CH_ + c)*N_ + nq;
        float e = __expf(d_pm[b] - Mx);
        L  = fmaf(d_pl[b], e, L);
        oa = fmaf(d_po[(size_t)b*32 + d], e, oa);
    }
    d_of[nq*E_ + h*HD_ + d] = oa / L;
}

// ---------------- D: out-proj + residual + layernorm ---------------------
__global__ void kepi(const float* __restrict__ x, const float* __restrict__ out_w,
                     const float* __restrict__ ln_g, const float* __restrict__ ln_b,
                     float* __restrict__ out) {
    int n = blockIdx.x, t = threadIdx.x;   // 256 threads
    __shared__ float so[128];
    __shared__ float red[256], red2[256];
    if (t < 128) so[t] = d_of[n*128 + t];
    __syncthreads();
    float r = x[n*256 + t];
    const float* wr = out_w + t*128;
    #pragma unroll 8
    for (int e = 0; e < 128; e++) r = fmaf(so[e], wr[e], r);
    red[t] = r; red2[t] = r*r;
    __syncthreads();
    for (int s = 128; s > 0; s >>= 1) {
        if (t < s) { red[t] += red[t + s]; red2[t] += red2[t + s]; }
        __syncthreads();
    }
    float mu  = red[0] * (1.f/256.f);
    float var = red2[0] * (1.f/256.f) - mu*mu;
    float inv = rsqrtf(var + 1e-5f);
    out[n*256 + t] = (r - mu) * inv * ln_g[t] + ln_b[t];
}

// ---------------- launch --------------------------------------------------
extern "C" void kernel_launch(void* const* d_in, const int* in_sizes, int n_in,
                              void* d_out, int out_size) {
    const float* x       = (const float*)d_in[0];
    const float* y       = (const float*)d_in[1];
    const float* x_pos   = (const float*)d_in[2];
    const float* y_pos   = (const float*)d_in[3];
    const float* theta_w = (const float*)d_in[4];
    const float* phi_w   = (const float*)d_in[5];
    const float* g_w     = (const float*)d_in[6];
    const float* q_w1    = (const float*)d_in[7];
    const float* q_b1    = (const float*)d_in[8];
    const float* q_w2    = (const float*)d_in[9];
    const float* q_b2    = (const float*)d_in[10];
    const float* k_w1    = (const float*)d_in[11];
    const float* k_b1    = (const float*)d_in[12];
    const float* k_w2    = (const float*)d_in[13];
    const float* k_b2    = (const float*)d_in[14];
    const float* out_w   = (const float*)d_in[15];
    const float* ln_g    = (const float*)d_in[16];
    const float* ln_b    = (const float*)d_in[17];
    float* out = (float*)d_out;

    cudaFuncSetAttribute(kattn, cudaFuncAttributeMaxDynamicSharedMemorySize, 91392);

    kfold<<<128, 128>>>(phi_w, g_w, k_w2, k_b2);
    kq<<<256, 128>>>(x, x_pos, theta_w, q_w1, q_b1, q_w2, q_b2);
    kproj<<<dim3(256, 4), 128>>>(x, y, phi_w, g_w);
    kattn<<<dim3(CH_, H_), 256, 91392>>>(x_pos, y_pos, k_w1, k_b1);
    kcomb<<<1024, 32>>>();
    kepi<<<256, 256>>>(x, out_w, ln_g, ln_b, out);
}

// round 7
// speedup vs baseline: 1.1231x; 1.1231x over previous
#include <cuda_runtime.h>
#include <math.h>

#define N_  256
#define M_  256
#define D_  256
#define E_  128
#define H_  4
#define HD_ 32
#define P_  64
#define CH_ 74    // key chunks per head (variable 3-4 tiles each)

// ---------------- packed fp32x2 helpers (Blackwell FFMA2 path) -----------
typedef unsigned long long u64;

__device__ __forceinline__ u64 pack2(float a, float b) {
    u64 r; asm("mov.b64 %0, {%1, %2};" : "=l"(r) : "f"(a), "f"(b)); return r;
}
__device__ __forceinline__ u64 dup2(float a) {
    u64 r; asm("mov.b64 %0, {%1, %1};" : "=l"(r) : "f"(a)); return r;
}
__device__ __forceinline__ void unpack2(u64 v, float& lo, float& hi) {
    asm("mov.b64 {%0, %1}, %2;" : "=f"(lo), "=f"(hi) : "l"(v));
}
__device__ __forceinline__ u64 fma2(u64 a, u64 b, u64 c) {
    u64 d; asm("fma.rn.f32x2 %0, %1, %2, %3;" : "=l"(d) : "l"(a), "l"(b), "l"(c)); return d;
}
__device__ __forceinline__ u64 add2(u64 a, u64 b) {
    u64 d; asm("add.rn.f32x2 %0, %1, %2;" : "=l"(d) : "l"(a), "l"(b)); return d;
}
__device__ __forceinline__ u64 mul2(u64 a, u64 b) {
    u64 d; asm("mul.rn.f32x2 %0, %1, %2;" : "=l"(d) : "l"(a), "l"(b)); return d;
}

// ---------------- device scratch (static, no allocations) ----------------
__device__ float d_q[N_*E_];                       // scaled queries [N][E]
__device__ float d_phix[N_*E_], d_nphiy[M_*E_];    // nphiy = NEGATED phi_y
__device__ float d_gx[N_*E_],  d_ngy[M_*E_];       // ngy = NEGATED g_y
__device__ float d_Wkp[E_*P_], d_Wkg[E_*P_];       // folded MLP2 @ proj weights
__device__ float d_bkp[E_],    d_bkg[E_];
__device__ float d_pm[H_*CH_*N_], d_pl[H_*CH_*N_]; // partial softmax stats
__device__ float d_po[H_*CH_*N_*HD_];              // partial outputs

// chunk c tile range: heavy chunks (c<34) have 4 tiles, light have 3
__device__ __forceinline__ void chunk_range(int c, int& t0, int& t1) {
    if (c < 34) { t0 = 4*c;            t1 = t0 + 4; }
    else        { t0 = 136 + 3*(c-34); t1 = t0 + 3; }
}

// ---------------- A: fused prep (fold + queries + projections) -----------
// 128 threads. blocks: [0,128) fold, [128,384) queries, [384,1408) proj
__global__ void kprep(const float* __restrict__ x, const float* __restrict__ y,
                      const float* __restrict__ x_pos,
                      const float* __restrict__ theta_w,
                      const float* __restrict__ phi_w, const float* __restrict__ g_w,
                      const float* __restrict__ q_w1, const float* __restrict__ q_b1,
                      const float* __restrict__ q_w2, const float* __restrict__ q_b2,
                      const float* __restrict__ k_w2, const float* __restrict__ k_b2) {
    int b = blockIdx.x, t = threadIdx.x;
    if (b < 128) {                      // -------- fold --------
        int e = b;
        if (t < 64) {
            float a = 0.f;
            for (int ep = 0; ep < 128; ep++)
                a = fmaf(phi_w[e*384 + 256 + ep], k_w2[ep*64 + t], a);
            d_Wkp[e*64 + t] = a;
        } else {
            int p = t - 64; float a = 0.f;
            for (int ep = 0; ep < 128; ep++)
                a = fmaf(g_w[e*384 + 256 + ep], k_w2[ep*64 + p], a);
            d_Wkg[e*64 + p] = a;
        }
        if (t == 0) {
            float a = 0.f;
            for (int ep = 0; ep < 128; ep++) a = fmaf(phi_w[e*384 + 256 + ep], k_b2[ep], a);
            d_bkp[e] = a;
        }
        if (t == 64) {
            float a = 0.f;
            for (int ep = 0; ep < 128; ep++) a = fmaf(g_w[e*384 + 256 + ep], k_b2[ep], a);
            d_bkg[e] = a;
        }
        return;
    }
    if (b < 384) {                      // -------- queries --------
        int n = b - 128;
        __shared__ float hq[64], qpe[128], sx[256];
        float xp0 = x_pos[n*3], xp1 = x_pos[n*3+1], xp2 = x_pos[n*3+2];
        if (t < 64)
            hq[t] = fmaxf(0.f, fmaf(q_w1[t*3], xp0, fmaf(q_w1[t*3+1], xp1,
                         fmaf(q_w1[t*3+2], xp2, q_b1[t]))));
        sx[t]       = x[n*256 + t];
        sx[t + 128] = x[n*256 + t + 128];
        __syncthreads();
        float a = q_b2[t];
        for (int p = 0; p < 64; p++) a = fmaf(hq[p], q_w2[t*64 + p], a);
        qpe[t] = a;
        __syncthreads();
        float s = 0.f;
        const float* tw = theta_w + t*384;
        #pragma unroll 8
        for (int d = 0; d < 256; d++) s = fmaf(sx[d], tw[d], s);
        #pragma unroll 8
        for (int e = 0; e < 128; e++) s = fmaf(qpe[e], tw[256 + e], s);
        d_q[n*128 + t] = s * 0.17677669529663687f;   // HD^-0.5
        return;
    }
    {                                   // -------- projections --------
        int idx = b - 384;              // 0..1023
        int n = idx & 255, which = idx >> 8;
        const float* src = (which & 1) ? y : x;
        const float* w   = (which < 2) ? phi_w : g_w;
        float sign = (which & 1) ? -1.f : 1.f;   // negate y-side
        float* out = (which == 0) ? d_phix : (which == 1) ? d_nphiy
                   : (which == 2) ? d_gx   : d_ngy;
        __shared__ float sx[256];
        sx[t]       = src[n*256 + t];
        sx[t + 128] = src[n*256 + t + 128];
        __syncthreads();
        float a = 0.f;
        const float* wr = w + t*384;
        #pragma unroll 8
        for (int d = 0; d < 256; d++) a = fmaf(sx[d], wr[d], a);
        out[n*128 + t] = a * sign;
    }
}

// ---------------- B: fused kv-gen + flash attention (split-K, f32x2) -----
// grid 296 CTAs, 256 threads. Thread t = query index AND per-tile key row n.
__global__ void __launch_bounds__(256, 2)
kattn(const float* __restrict__ x_pos, const float* __restrict__ y_pos,
      const float* __restrict__ k_w1, const float* __restrict__ k_b1) {
    extern __shared__ float sm[];
    float* ks   = sm;            // [256][36]
    float* vs   = sm + 9216;     // [256][36]
    float* WkpT = sm + 18432;    // [64][32]  (transposed head slice)
    float* WkgT = sm + 20480;    // [64][32]
    float* kw1s = sm + 22528;    // [64*3]
    float* kb1s = sm + 22720;    // [64]
    u64*   bkp2 = (u64*)(sm + 22784); // [16]
    u64*   bkg2 = bkp2 + 16;          // [16]   total 91392 bytes

    // bid -> (chunk, head). bids [0,136) heavy (4 tiles), [136,296) light (3).
    // Classic placement pairs bid and bid+148 on one SM -> heavy+light mix.
    int bid = blockIdx.x, t = threadIdx.x;
    int c, h;
    if (bid < 136) { c = bid % 34; h = bid / 34; }       // heavy: c in [0,34)
    else {
        int u = bid - 136;                               // u in [0,160)
        c = 34 + (u % 40); h = u / 40;                   // light: c in [34,74)
    }
    int t0, t1; chunk_range(c, t0, t1);

    for (int i = t; i < 2048; i += 256) {
        int p = i >> 5, d = i & 31;
        WkpT[i] = d_Wkp[(h*32 + d)*64 + p];
        WkgT[i] = d_Wkg[(h*32 + d)*64 + p];
    }
    for (int i = t; i < 192; i += 256) kw1s[i] = k_w1[i];
    if (t < 64) kb1s[t] = k_b1[t];
    if (t < 16) bkp2[t] = pack2(d_bkp[h*32 + 2*t], d_bkp[h*32 + 2*t + 1]);
    else if (t < 32) { int j = t - 16; bkg2[j] = pack2(d_bkg[h*32 + 2*j], d_bkg[h*32 + 2*j + 1]); }
    __syncthreads();

    u64 o2[16];
    #pragma unroll
    for (int i = 0; i < 16; i++) o2[i] = 0ULL;
    float mr = -INFINITY, lr = 0.f;

    float xp0 = x_pos[t*3], xp1 = x_pos[t*3+1], xp2 = x_pos[t*3+2];

    for (int m = t0; m < t1; ++m) {
        float r0 = xp0 - y_pos[m*3];
        float r1 = xp1 - y_pos[m*3+1];
        float r2 = xp2 - y_pos[m*3+2];

        u64 acc2[16];
        // ---- k row for key (m, n=t), head slice ----
        {
            const ulonglong2* px = (const ulonglong2*)(d_phix  + t*E_ + h*HD_);
            const ulonglong2* py = (const ulonglong2*)(d_nphiy + m*E_ + h*HD_);
            #pragma unroll
            for (int i = 0; i < 8; i++) {
                ulonglong2 a = px[i], b = py[i];
                acc2[2*i]   = add2(add2(a.x, b.x), bkp2[2*i]);
                acc2[2*i+1] = add2(add2(a.y, b.y), bkp2[2*i+1]);
            }
        }
        #pragma unroll 4
        for (int p = 0; p < 64; p++) {
            float h1 = fmaxf(0.f, fmaf(kw1s[p*3], r0, fmaf(kw1s[p*3+1], r1,
                            fmaf(kw1s[p*3+2], r2, kb1s[p]))));
            u64 hh = dup2(h1);
            const ulonglong2* w = (const ulonglong2*)(WkpT + p*32);
            #pragma unroll
            for (int i = 0; i < 8; i++) {
                ulonglong2 wv = w[i];
                acc2[2*i]   = fma2(hh, wv.x, acc2[2*i]);
                acc2[2*i+1] = fma2(hh, wv.y, acc2[2*i+1]);
            }
        }
        {
            ulonglong2* kd = (ulonglong2*)(ks + t*36);
            #pragma unroll
            for (int i = 0; i < 8; i++) kd[i] = make_ulonglong2(acc2[2*i], acc2[2*i+1]);
        }
        // ---- v row (reuse acc) ----
        {
            const ulonglong2* px = (const ulonglong2*)(d_gx  + t*E_ + h*HD_);
            const ulonglong2* py = (const ulonglong2*)(d_ngy + m*E_ + h*HD_);
            #pragma unroll
            for (int i = 0; i < 8; i++) {
                ulonglong2 a = px[i], b = py[i];
                acc2[2*i]   = add2(add2(a.x, b.x), bkg2[2*i]);
                acc2[2*i+1] = add2(add2(a.y, b.y), bkg2[2*i+1]);
            }
        }
        #pragma unroll 4
        for (int p = 0; p < 64; p++) {
            float h1 = fmaxf(0.f, fmaf(kw1s[p*3], r0, fmaf(kw1s[p*3+1], r1,
                            fmaf(kw1s[p*3+2], r2, kb1s[p]))));
            u64 hh = dup2(h1);
            const ulonglong2* w = (const ulonglong2*)(WkgT + p*32);
            #pragma unroll
            for (int i = 0; i < 8; i++) {
                ulonglong2 wv = w[i];
                acc2[2*i]   = fma2(hh, wv.x, acc2[2*i]);
                acc2[2*i+1] = fma2(hh, wv.y, acc2[2*i+1]);
            }
        }
        {
            ulonglong2* vd = (ulonglong2*)(vs + t*36);
            #pragma unroll
            for (int i = 0; i < 8; i++) vd[i] = make_ulonglong2(acc2[2*i], acc2[2*i+1]);
        }
        __syncthreads();

        // ---- load q (after kv-gen to keep gen-phase reg pressure low) ----
        u64 q2[16];
        {
            const ulonglong2* qp = (const ulonglong2*)(d_q + t*E_ + h*HD_);
            #pragma unroll
            for (int i = 0; i < 8; i++) { ulonglong2 v = qp[i]; q2[2*i] = v.x; q2[2*i+1] = v.y; }
        }

        // ---- online-softmax attention over this 256-key tile ----
        for (int kb = 0; kb < 256; kb += 8) {
            float s[8];
            #pragma unroll
            for (int k8 = 0; k8 < 8; k8++) {
                const ulonglong2* kk = (const ulonglong2*)(ks + (kb + k8)*36);
                u64 aa = 0ULL, ab = 0ULL;
                #pragma unroll
                for (int i = 0; i < 8; i++) {
                    ulonglong2 kv = kk[i];
                    aa = fma2(q2[2*i],   kv.x, aa);
                    ab = fma2(q2[2*i+1], kv.y, ab);
                }
                float al, ah, bl, bh;
                unpack2(aa, al, ah); unpack2(ab, bl, bh);
                s[k8] = (al + ah) + (bl + bh);
            }
            float mn = mr;
            #pragma unroll
            for (int k8 = 0; k8 < 8; k8++) mn = fmaxf(mn, s[k8]);
            float scale = __expf(mr - mn);
            float ls = 0.f;
            #pragma unroll
            for (int k8 = 0; k8 < 8; k8++) { s[k8] = __expf(s[k8] - mn); ls += s[k8]; }
            lr = fmaf(lr, scale, ls);
            mr = mn;
            u64 ss = dup2(scale);
            #pragma unroll
            for (int i = 0; i < 16; i++) o2[i] = mul2(o2[i], ss);
            #pragma unroll
            for (int k8 = 0; k8 < 8; k8++) {
                const ulonglong2* vv = (const ulonglong2*)(vs + (kb + k8)*36);
                u64 pp = dup2(s[k8]);
                #pragma unroll
                for (int i = 0; i < 8; i++) {
                    ulonglong2 v = vv[i];
                    o2[2*i]   = fma2(pp, v.x, o2[2*i]);
                    o2[2*i+1] = fma2(pp, v.y, o2[2*i+1]);
                }
            }
        }
        __syncthreads();
    }

    int base = (h*CH_ + c)*N_ + t;
    d_pm[base] = mr;
    d_pl[base] = lr;
    ulonglong2* op = (ulonglong2*)(d_po + (size_t)base*32);
    #pragma unroll
    for (int i = 0; i < 8; i++) op[i] = make_ulonglong2(o2[2*i], o2[2*i+1]);
}

// ---------------- C: combine + out-proj + residual + layernorm -----------
__global__ void kfinal(const float* __restrict__ x, const float* __restrict__ out_w,
                       const float* __restrict__ ln_g, const float* __restrict__ ln_b,
                       float* __restrict__ out) {
    int n = blockIdx.x, t = threadIdx.x;   // 256 threads
    __shared__ float so[128];
    __shared__ float red[256], red2[256];
    if (t < 128) {
        int h = t >> 5, d = t & 31;
        float Mx = -INFINITY;
        #pragma unroll 2
        for (int c = 0; c < CH_; c++)
            Mx = fmaxf(Mx, d_pm[(h*CH_ + c)*N_ + n]);
        float L = 0.f, oa = 0.f;
        #pragma unroll 2
        for (int c = 0; c < CH_; c++) {
            int b = (h*CH_ + c)*N_ + n;
            float e = __expf(d_pm[b] - Mx);
            L  = fmaf(d_pl[b], e, L);
            oa = fmaf(d_po[(size_t)b*32 + d], e, oa);
        }
        so[t] = oa / L;
    }
    __syncthreads();
    float r = x[n*256 + t];
    const float* wr = out_w + t*128;
    #pragma unroll 8
    for (int e = 0; e < 128; e++) r = fmaf(so[e], wr[e], r);
    red[t] = r; red2[t] = r*r;
    __syncthreads();
    for (int s = 128; s > 0; s >>= 1) {
        if (t < s) { red[t] += red[t + s]; red2[t] += red2[t + s]; }
        __syncthreads();
    }
    float mu  = red[0] * (1.f/256.f);
    float var = red2[0] * (1.f/256.f) - mu*mu;
    float inv = rsqrtf(var + 1e-5f);
    out[n*256 + t] = (r - mu) * inv * ln_g[t] + ln_b[t];
}

// ---------------- launch --------------------------------------------------
extern "C" void kernel_launch(void* const* d_in, const int* in_sizes, int n_in,
                              void* d_out, int out_size) {
    const float* x       = (const float*)d_in[0];
    const float* y       = (const float*)d_in[1];
    const float* x_pos   = (const float*)d_in[2];
    const float* y_pos   = (const float*)d_in[3];
    const float* theta_w = (const float*)d_in[4];
    const float* phi_w   = (const float*)d_in[5];
    const float* g_w     = (const float*)d_in[6];
    const float* q_w1    = (const float*)d_in[7];
    const float* q_b1    = (const float*)d_in[8];
    const float* q_w2    = (const float*)d_in[9];
    const float* q_b2    = (const float*)d_in[10];
    const float* k_w1    = (const float*)d_in[11];
    const float* k_b1    = (const float*)d_in[12];
    const float* k_w2    = (const float*)d_in[13];
    const float* k_b2    = (const float*)d_in[14];
    const float* out_w   = (const float*)d_in[15];
    const float* ln_g    = (const float*)d_in[16];
    const float* ln_b    = (const float*)d_in[17];
    float* out = (float*)d_out;

    cudaFuncSetAttribute(kattn, cudaFuncAttributeMaxDynamicSharedMemorySize, 91392);

    kprep<<<1408, 128>>>(x, y, x_pos, theta_w, phi_w, g_w,
                         q_w1, q_b1, q_w2, q_b2, k_w2, k_b2);
    kattn<<<296, 256, 91392>>>(x_pos, y_pos, k_w1, k_b1);
    kfinal<<<256, 256>>>(x, out_w, ln_g, ln_b, out);
}

// round 8
// speedup vs baseline: 1.4959x; 1.3320x over previous
#include <cuda_runtime.h>
#include <math.h>

#define N_  256
#define M_  256
#define D_  256
#define E_  128
#define H_  4
#define HD_ 32
#define P_  64
#define CH_ 74    // key chunks per head (variable 3-4 tiles each)

// ---------------- packed fp32x2 helpers (Blackwell FFMA2 path) -----------
typedef unsigned long long u64;

__device__ __forceinline__ u64 pack2(float a, float b) {
    u64 r; asm("mov.b64 %0, {%1, %2};" : "=l"(r) : "f"(a), "f"(b)); return r;
}
__device__ __forceinline__ u64 dup2(float a) {
    u64 r; asm("mov.b64 %0, {%1, %1};" : "=l"(r) : "f"(a)); return r;
}
__device__ __forceinline__ void unpack2(u64 v, float& lo, float& hi) {
    asm("mov.b64 {%0, %1}, %2;" : "=f"(lo), "=f"(hi) : "l"(v));
}
__device__ __forceinline__ u64 fma2(u64 a, u64 b, u64 c) {
    u64 d; asm("fma.rn.f32x2 %0, %1, %2, %3;" : "=l"(d) : "l"(a), "l"(b), "l"(c)); return d;
}
__device__ __forceinline__ u64 add2(u64 a, u64 b) {
    u64 d; asm("add.rn.f32x2 %0, %1, %2;" : "=l"(d) : "l"(a), "l"(b)); return d;
}
__device__ __forceinline__ u64 mul2(u64 a, u64 b) {
    u64 d; asm("mul.rn.f32x2 %0, %1, %2;" : "=l"(d) : "l"(a), "l"(b)); return d;
}

// ---------------- device scratch (static, no allocations) ----------------
__device__ float d_qpe[N_*E_];                     // pos-MLP query embedding
__device__ float d_q[N_*E_];                       // scaled queries [N][E]
__device__ float d_phix[N_*E_], d_nphiy[M_*E_];    // nphiy = NEGATED phi_y
__device__ float d_gx[N_*E_],  d_ngy[M_*E_];       // ngy = NEGATED g_y
__device__ float d_Wkp[E_*P_], d_Wkg[E_*P_];       // folded MLP2 @ proj weights
__device__ float d_bkp[E_],    d_bkg[E_];
__device__ float d_pm[H_*CH_*N_], d_pl[H_*CH_*N_]; // partial softmax stats
__device__ float d_po[H_*CH_*N_*HD_];              // partial outputs

// chunk c tile range: heavy chunks (c<34) have 4 tiles, light have 3
__device__ __forceinline__ void chunk_range(int c, int& t0, int& t1) {
    if (c < 34) { t0 = 4*c;            t1 = t0 + 4; }
    else        { t0 = 136 + 3*(c-34); t1 = t0 + 3; }
}

// ---------------- A0: fold phi_w[:,D:] @ k_w2 -> Wkp / Wkg ---------------
__global__ void kfold(const float* __restrict__ phi_w, const float* __restrict__ g_w,
                      const float* __restrict__ k_w2, const float* __restrict__ k_b2) {
    int e = blockIdx.x, t = threadIdx.x;   // 128 threads
    if (t < 64) {
        float a = 0.f;
        for (int ep = 0; ep < 128; ep++)
            a = fmaf(phi_w[e*384 + 256 + ep], k_w2[ep*64 + t], a);
        d_Wkp[e*64 + t] = a;
    } else {
        int p = t - 64; float a = 0.f;
        for (int ep = 0; ep < 128; ep++)
            a = fmaf(g_w[e*384 + 256 + ep], k_w2[ep*64 + p], a);
        d_Wkg[e*64 + p] = a;
    }
    if (t == 0) {
        float a = 0.f;
        for (int ep = 0; ep < 128; ep++) a = fmaf(phi_w[e*384 + 256 + ep], k_b2[ep], a);
        d_bkp[e] = a;
    }
    if (t == 64) {
        float a = 0.f;
        for (int ep = 0; ep < 128; ep++) a = fmaf(g_w[e*384 + 256 + ep], k_b2[ep], a);
        d_bkg[e] = a;
    }
}

// ---------------- A1: query pos-MLP embedding (coalesced, smem-staged) ---
// grid 8, 256 threads. Block handles 32 queries.
__global__ void __launch_bounds__(256)
kqpe(const float* __restrict__ x_pos,
     const float* __restrict__ q_w1, const float* __restrict__ q_b1,
     const float* __restrict__ q_w2, const float* __restrict__ q_b2) {
    __shared__ float sW[128*65];   // q_w2 [e][p], pad 65
    __shared__ float hq[32*65];    // hidden [n][p], pad 65
    __shared__ float w1s[192], b1s[64], b2s[128];
    int t = threadIdx.x, n0 = blockIdx.x * 32;

    for (int i = t; i < 8192; i += 256) {        // coalesced q_w2 load
        int e = i >> 6, p = i & 63;
        sW[e*65 + p] = q_w2[i];
    }
    if (t < 192) w1s[t] = q_w1[t];
    if (t < 64)  b1s[t] = q_b1[t];
    if (t < 128) b2s[t] = q_b2[t];
    __syncthreads();

    for (int i = t; i < 2048; i += 256) {        // hidden layer
        int n = i >> 6, p = i & 63;
        float xp0 = x_pos[(n0+n)*3], xp1 = x_pos[(n0+n)*3+1], xp2 = x_pos[(n0+n)*3+2];
        hq[n*65 + p] = fmaxf(0.f, fmaf(w1s[p*3], xp0, fmaf(w1s[p*3+1], xp1,
                              fmaf(w1s[p*3+2], xp2, b1s[p]))));
    }
    __syncthreads();

    int ce = t & 31, rg = t >> 5;                // 8 groups of 4 rows
    float acc[4][4];
    #pragma unroll
    for (int i = 0; i < 4; i++)
        #pragma unroll
        for (int j = 0; j < 4; j++) acc[i][j] = b2s[ce + 32*j];
    for (int p = 0; p < 64; p++) {
        float w0 = sW[(ce     )*65 + p], w1 = sW[(ce+32)*65 + p];
        float w2 = sW[(ce+64)*65 + p],  w3 = sW[(ce+96)*65 + p];
        #pragma unroll
        for (int i = 0; i < 4; i++) {
            float xv = hq[(rg*4 + i)*65 + p];
            acc[i][0] = fmaf(xv, w0, acc[i][0]);
            acc[i][1] = fmaf(xv, w1, acc[i][1]);
            acc[i][2] = fmaf(xv, w2, acc[i][2]);
            acc[i][3] = fmaf(xv, w3, acc[i][3]);
        }
    }
    #pragma unroll
    for (int i = 0; i < 4; i++)
        #pragma unroll
        for (int j = 0; j < 4; j++)
            d_qpe[(n0 + rg*4 + i)*128 + ce + 32*j] = acc[i][j];
}

// ---------------- A2: tiled GEMM for q / phix / nphiy / gx / ngy ---------
// grid 40 (= 5 jobs x 8 row tiles of 32), 256 threads.
__global__ void __launch_bounds__(256)
kgemm(const float* __restrict__ x, const float* __restrict__ y,
      const float* __restrict__ theta_w, const float* __restrict__ phi_w,
      const float* __restrict__ g_w) {
    __shared__ float ws[128*65];   // weight tile [e][k], pad 65
    __shared__ float xs[32*65];    // act tile [n][k], pad 65
    int t = threadIdx.x;
    int job = blockIdx.x >> 3, rt = blockIdx.x & 7;
    int n0 = rt * 32;

    const float* W   = (job == 0) ? theta_w : (job <= 2 ? phi_w : g_w);
    const float* src = (job == 2 || job == 4) ? y : x;
    int   K    = (job == 0) ? 384 : 256;
    float mult = (job == 0) ? 0.17677669529663687f
               : (job == 2 || job == 4) ? -1.f : 1.f;
    float* out = (job == 0) ? d_q : (job == 1) ? d_phix : (job == 2) ? d_nphiy
               : (job == 3) ? d_gx : d_ngy;

    int ce = t & 31, rg = t >> 5;
    float acc[4][4];
    #pragma unroll
    for (int i = 0; i < 4; i++)
        #pragma unroll
        for (int j = 0; j < 4; j++) acc[i][j] = 0.f;

    for (int k0 = 0; k0 < K; k0 += 64) {
        for (int i = t; i < 8192; i += 256) {        // weight tile, coalesced
            int e = i >> 6, k = i & 63;
            ws[e*65 + k] = W[e*384 + k0 + k];
        }
        for (int i = t; i < 2048; i += 256) {        // activation tile
            int n = i >> 6, k = i & 63;
            float v;
            if (job == 0 && k0 >= 256) v = d_qpe[(n0+n)*128 + (k0 - 256) + k];
            else                       v = src[(n0+n)*256 + k0 + k];
            xs[n*65 + k] = v;
        }
        __syncthreads();
        #pragma unroll 4
        for (int k = 0; k < 64; k++) {
            float w0 = ws[(ce     )*65 + k], w1 = ws[(ce+32)*65 + k];
            float w2 = ws[(ce+64)*65 + k],  w3 = ws[(ce+96)*65 + k];
            #pragma unroll
            for (int i = 0; i < 4; i++) {
                float xv = xs[(rg*4 + i)*65 + k];
                acc[i][0] = fmaf(xv, w0, acc[i][0]);
                acc[i][1] = fmaf(xv, w1, acc[i][1]);
                acc[i][2] = fmaf(xv, w2, acc[i][2]);
                acc[i][3] = fmaf(xv, w3, acc[i][3]);
            }
        }
        __syncthreads();
    }
    #pragma unroll
    for (int i = 0; i < 4; i++)
        #pragma unroll
        for (int j = 0; j < 4; j++)
            out[(n0 + rg*4 + i)*128 + ce + 32*j] = acc[i][j] * mult;
}

// ---------------- B: fused kv-gen + flash attention (split-K, f32x2) -----
// grid 296 CTAs, 256 threads. Thread t = query index AND per-tile key row n.
__global__ void __launch_bounds__(256, 2)
kattn(const float* __restrict__ x_pos, const float* __restrict__ y_pos,
      const float* __restrict__ k_w1, const float* __restrict__ k_b1) {
    extern __shared__ float sm[];
    float* ks   = sm;            // [256][36]
    float* vs   = sm + 9216;     // [256][36]
    float* WkpT = sm + 18432;    // [64][32]  (transposed head slice)
    float* WkgT = sm + 20480;    // [64][32]
    float* kw1s = sm + 22528;    // [64*3]
    float* kb1s = sm + 22720;    // [64]
    u64*   bkp2 = (u64*)(sm + 22784); // [16]
    u64*   bkg2 = bkp2 + 16;          // [16]   total 91392 bytes

    // bid -> (chunk, head). bids [0,136) heavy (4 tiles), [136,296) light (3).
    int bid = blockIdx.x, t = threadIdx.x;
    int c, h;
    if (bid < 136) { c = bid % 34; h = bid / 34; }       // heavy: c in [0,34)
    else {
        int u = bid - 136;                               // u in [0,160)
        c = 34 + (u % 40); h = u / 40;                   // light: c in [34,74)
    }
    int t0, t1; chunk_range(c, t0, t1);

    for (int i = t; i < 2048; i += 256) {
        int p = i >> 5, d = i & 31;
        WkpT[i] = d_Wkp[(h*32 + d)*64 + p];
        WkgT[i] = d_Wkg[(h*32 + d)*64 + p];
    }
    for (int i = t; i < 192; i += 256) kw1s[i] = k_w1[i];
    if (t < 64) kb1s[t] = k_b1[t];
    if (t < 16) bkp2[t] = pack2(d_bkp[h*32 + 2*t], d_bkp[h*32 + 2*t + 1]);
    else if (t < 32) { int j = t - 16; bkg2[j] = pack2(d_bkg[h*32 + 2*j], d_bkg[h*32 + 2*j + 1]); }
    __syncthreads();

    u64 o2[16];
    #pragma unroll
    for (int i = 0; i < 16; i++) o2[i] = 0ULL;
    float mr = -INFINITY, lr = 0.f;

    float xp0 = x_pos[t*3], xp1 = x_pos[t*3+1], xp2 = x_pos[t*3+2];

    for (int m = t0; m < t1; ++m) {
        float r0 = xp0 - y_pos[m*3];
        float r1 = xp1 - y_pos[m*3+1];
        float r2 = xp2 - y_pos[m*3+2];

        u64 acc2[16];
        // ---- k row for key (m, n=t), head slice ----
        {
            const ulonglong2* px = (const ulonglong2*)(d_phix  + t*E_ + h*HD_);
            const ulonglong2* py = (const ulonglong2*)(d_nphiy + m*E_ + h*HD_);
            #pragma unroll
            for (int i = 0; i < 8; i++) {
                ulonglong2 a = px[i], b = py[i];
                acc2[2*i]   = add2(add2(a.x, b.x), bkp2[2*i]);
                acc2[2*i+1] = add2(add2(a.y, b.y), bkp2[2*i+1]);
            }
        }
        #pragma unroll 4
        for (int p = 0; p < 64; p++) {
            float h1 = fmaxf(0.f, fmaf(kw1s[p*3], r0, fmaf(kw1s[p*3+1], r1,
                            fmaf(kw1s[p*3+2], r2, kb1s[p]))));
            u64 hh = dup2(h1);
            const ulonglong2* w = (const ulonglong2*)(WkpT + p*32);
            #pragma unroll
            for (int i = 0; i < 8; i++) {
                ulonglong2 wv = w[i];
                acc2[2*i]   = fma2(hh, wv.x, acc2[2*i]);
                acc2[2*i+1] = fma2(hh, wv.y, acc2[2*i+1]);
            }
        }
        {
            ulonglong2* kd = (ulonglong2*)(ks + t*36);
            #pragma unroll
            for (int i = 0; i < 8; i++) kd[i] = make_ulonglong2(acc2[2*i], acc2[2*i+1]);
        }
        // ---- v row (reuse acc) ----
        {
            const ulonglong2* px = (const ulonglong2*)(d_gx  + t*E_ + h*HD_);
            const ulonglong2* py = (const ulonglong2*)(d_ngy + m*E_ + h*HD_);
            #pragma unroll
            for (int i = 0; i < 8; i++) {
                ulonglong2 a = px[i], b = py[i];
                acc2[2*i]   = add2(add2(a.x, b.x), bkg2[2*i]);
                acc2[2*i+1] = add2(add2(a.y, b.y), bkg2[2*i+1]);
            }
        }
        #pragma unroll 4
        for (int p = 0; p < 64; p++) {
            float h1 = fmaxf(0.f, fmaf(kw1s[p*3], r0, fmaf(kw1s[p*3+1], r1,
                            fmaf(kw1s[p*3+2], r2, kb1s[p]))));
            u64 hh = dup2(h1);
            const ulonglong2* w = (const ulonglong2*)(WkgT + p*32);
            #pragma unroll
            for (int i = 0; i < 8; i++) {
                ulonglong2 wv = w[i];
                acc2[2*i]   = fma2(hh, wv.x, acc2[2*i]);
                acc2[2*i+1] = fma2(hh, wv.y, acc2[2*i+1]);
            }
        }
        {
            ulonglong2* vd = (ulonglong2*)(vs + t*36);
            #pragma unroll
            for (int i = 0; i < 8; i++) vd[i] = make_ulonglong2(acc2[2*i], acc2[2*i+1]);
        }
        __syncthreads();

        // ---- load q (after kv-gen to keep gen-phase reg pressure low) ----
        u64 q2[16];
        {
            const ulonglong2* qp = (const ulonglong2*)(d_q + t*E_ + h*HD_);
            #pragma unroll
            for (int i = 0; i < 8; i++) { ulonglong2 v = qp[i]; q2[2*i] = v.x; q2[2*i+1] = v.y; }
        }

        // ---- online-softmax attention over this 256-key tile ----
        for (int kb = 0; kb < 256; kb += 8) {
            float s[8];
            #pragma unroll
            for (int k8 = 0; k8 < 8; k8++) {
                const ulonglong2* kk = (const ulonglong2*)(ks + (kb + k8)*36);
                u64 aa = 0ULL, ab = 0ULL;
                #pragma unroll
                for (int i = 0; i < 8; i++) {
                    ulonglong2 kv = kk[i];
                    aa = fma2(q2[2*i],   kv.x, aa);
                    ab = fma2(q2[2*i+1], kv.y, ab);
                }
                float al, ah, bl, bh;
                unpack2(aa, al, ah); unpack2(ab, bl, bh);
                s[k8] = (al + ah) + (bl + bh);
            }
            float mn = mr;
            #pragma unroll
            for (int k8 = 0; k8 < 8; k8++) mn = fmaxf(mn, s[k8]);
            float scale = __expf(mr - mn);
            float ls = 0.f;
            #pragma unroll
            for (int k8 = 0; k8 < 8; k8++) { s[k8] = __expf(s[k8] - mn); ls += s[k8]; }
            lr = fmaf(lr, scale, ls);
            mr = mn;
            u64 ss = dup2(scale);
            #pragma unroll
            for (int i = 0; i < 16; i++) o2[i] = mul2(o2[i], ss);
            #pragma unroll
            for (int k8 = 0; k8 < 8; k8++) {
                const ulonglong2* vv = (const ulonglong2*)(vs + (kb + k8)*36);
                u64 pp = dup2(s[k8]);
                #pragma unroll
                for (int i = 0; i < 8; i++) {
                    ulonglong2 v = vv[i];
                    o2[2*i]   = fma2(pp, v.x, o2[2*i]);
                    o2[2*i+1] = fma2(pp, v.y, o2[2*i+1]);
                }
            }
        }
        __syncthreads();
    }

    int base = (h*CH_ + c)*N_ + t;
    d_pm[base] = mr;
    d_pl[base] = lr;
    ulonglong2* op = (ulonglong2*)(d_po + (size_t)base*32);
    #pragma unroll
    for (int i = 0; i < 8; i++) op[i] = make_ulonglong2(o2[2*i], o2[2*i+1]);
}

// ---------------- C: combine + out-proj + residual + layernorm -----------
__global__ void kfinal(const float* __restrict__ x, const float* __restrict__ out_w,
                       const float* __restrict__ ln_g, const float* __restrict__ ln_b,
                       float* __restrict__ out) {
    int n = blockIdx.x, t = threadIdx.x;   // 256 threads
    __shared__ float so[128];
    __shared__ float red[256], red2[256];
    if (t < 128) {
        int h = t >> 5, d = t & 31;
        float Mx = -INFINITY;
        #pragma unroll 2
        for (int c = 0; c < CH_; c++)
            Mx = fmaxf(Mx, d_pm[(h*CH_ + c)*N_ + n]);
        float L = 0.f, oa = 0.f;
        #pragma unroll 2
        for (int c = 0; c < CH_; c++) {
            int b = (h*CH_ + c)*N_ + n;
            float e = __expf(d_pm[b] - Mx);
            L  = fmaf(d_pl[b], e, L);
            oa = fmaf(d_po[(size_t)b*32 + d], e, oa);
        }
        so[t] = oa / L;
    }
    __syncthreads();
    float r = x[n*256 + t];
    const float* wr = out_w + t*128;
    #pragma unroll 8
    for (int e = 0; e < 128; e++) r = fmaf(so[e], wr[e], r);
    red[t] = r; red2[t] = r*r;
    __syncthreads();
    for (int s = 128; s > 0; s >>= 1) {
        if (t < s) { red[t] += red[t + s]; red2[t] += red2[t + s]; }
        __syncthreads();
    }
    float mu  = red[0] * (1.f/256.f);
    float var = red2[0] * (1.f/256.f) - mu*mu;
    float inv = rsqrtf(var + 1e-5f);
    out[n*256 + t] = (r - mu) * inv * ln_g[t] + ln_b[t];
}

// ---------------- launch --------------------------------------------------
extern "C" void kernel_launch(void* const* d_in, const int* in_sizes, int n_in,
                              void* d_out, int out_size) {
    const float* x       = (const float*)d_in[0];
    const float* y       = (const float*)d_in[1];
    const float* x_pos   = (const float*)d_in[2];
    const float* y_pos   = (const float*)d_in[3];
    const float* theta_w = (const float*)d_in[4];
    const float* phi_w   = (const float*)d_in[5];
    const float* g_w     = (const float*)d_in[6];
    const float* q_w1    = (const float*)d_in[7];
    const float* q_b1    = (const float*)d_in[8];
    const float* q_w2    = (const float*)d_in[9];
    const float* q_b2    = (const float*)d_in[10];
    const float* k_w1    = (const float*)d_in[11];
    const float* k_b1    = (const float*)d_in[12];
    const float* k_w2    = (const float*)d_in[13];
    const float* k_b2    = (const float*)d_in[14];
    const float* out_w   = (const float*)d_in[15];
    const float* ln_g    = (const float*)d_in[16];
    const float* ln_b    = (const float*)d_in[17];
    float* out = (float*)d_out;

    cudaFuncSetAttribute(kattn, cudaFuncAttributeMaxDynamicSharedMemorySize, 91392);

    kfold<<<128, 128>>>(phi_w, g_w, k_w2, k_b2);
    kqpe<<<8, 256>>>(x_pos, q_w1, q_b1, q_w2, q_b2);
    kgemm<<<40, 256>>>(x, y, theta_w, phi_w, g_w);
    kattn<<<296, 256, 91392>>>(x_pos, y_pos, k_w1, k_b1);
    kfinal<<<256, 256>>>(x, out_w, ln_g, ln_b, out);
}